// round 11
// baseline (speedup 1.0000x reference)
#include <cuda_runtime.h>

#define NT   24
#define FUT  48
#define NSTEP (NT + FUT)
#define NP   8                 // batch pairs per block (one pair = 2 warps)
#define NTHREADS (NP * 64)     // 512
#define GRID (4096 / NP)

typedef unsigned long long u64;

// ---- dynamic smem layout (float offsets) ----
#define OFF_WL    0                      // 512 rows x 64: w_ih cols 0..255, w_hh 256..511 (swizzled)
#define OFF_WG    (OFF_WL + 512*64)      // 128 rows x 64: g1wT 0..63, g2wT 64..127 (swizzled)
#define OFF_WD1   (OFF_WG + 128*64)      // 32 rows x 64: dw1T (swizzled)
#define OFF_ENCW  (OFF_WD1 + 32*64)      // 704 plain [k*64+h]
#define OFF_DW2   (OFF_ENCW + 704)       // 192
#define OFF_ENCB  (OFF_DW2 + 192)        // 64
#define OFF_G1B   (OFF_ENCB + 64)        // 64
#define OFF_G2B   (OFF_G1B + 64)         // 64
#define OFF_BSUM  (OFF_G2B + 64)         // 256
#define OFF_DB1   (OFF_BSUM + 256)       // 32
#define OFF_DB2   (OFF_DB1 + 32)         // 8 + 8 pad
#define OFF_PW    (OFF_DB2 + 16)
// per-pair region
#define PSB   0        // 448: enc-out / s1 / s2 ; gate-exchange X1 (g,o) after gates GEMM
#define PHB   448      // 448: hx
#define PX0   896      // 448: xs staging / gate-exchange X0 (i,f) / decoder dbuf
#define PADJ  1344     // 56
#define PPRED 1400     // 48
#define PSTAT 1448     // 40 -> 1488, pad
#define PW_FLOATS 1496
#define SMEM_FLOATS (OFF_PW + NP * PW_FLOATS)

__device__ __forceinline__ float sigf(float x) { return 1.0f / (1.0f + __expf(-x)); }
__device__ __forceinline__ float tanhfast(float x) { return 2.0f / (1.0f + __expf(-2.0f * x)) - 1.0f; }

__device__ __forceinline__ u64 fma2(u64 a, u64 b, u64 c) {
    u64 d;
    asm("fma.rn.f32x2 %0, %1, %2, %3;" : "=l"(d) : "l"(a), "l"(b), "l"(c));
    return d;
}
__device__ __forceinline__ u64 pk2(float lo, float hi) {
    u64 v;
    asm("mov.b64 %0, {%1, %2};" : "=l"(v) : "f"(lo), "f"(hi));
    return v;
}
__device__ __forceinline__ float hadd(u64 v) {
    float lo, hi;
    asm("mov.b64 {%0, %1}, %2;" : "=f"(lo), "=f"(hi) : "l"(v));
    return lo + hi;
}

// swizzled word offset for 64-float weight rows: quad index rotated by row
__device__ __forceinline__ int swz(int row, int k) {
    return row * 64 + (((k >> 2) + row) & 15) * 4 + (k & 3);
}

__global__ void __launch_bounds__(NTHREADS, 1) stgnn_kernel(
    const float* __restrict__ x_history, const float* __restrict__ adj,
    const float* __restrict__ enc_w, const float* __restrict__ enc_b,
    const float* __restrict__ g1w, const float* __restrict__ g1b,
    const float* __restrict__ g2w, const float* __restrict__ g2b,
    const float* __restrict__ w_ih, const float* __restrict__ w_hh,
    const float* __restrict__ b_ih, const float* __restrict__ b_hh,
    const float* __restrict__ dw1, const float* __restrict__ db1,
    const float* __restrict__ dw2, const float* __restrict__ db2,
    float* __restrict__ out)
{
    extern __shared__ float sm[];
    const int tid  = threadIdx.x;
    const int lane = tid & 31;
    const int wrp  = tid >> 5;
    const int wip  = wrp & 1;       // warp-in-pair: 0 = i,f / h-lo ; 1 = g,o / h-hi
    const int pr   = wrp >> 1;      // pair index 0..7
    const int pbid = 1 + pr;        // named barrier id
    const int hme  = lane + 32 * wip;

    // ================= block-wide weight staging =================
    for (int idx = tid; idx < 512 * 64; idx += NTHREADS) {
        int col = idx >> 6, k = idx & 63;
        float v = (col < 256) ? w_ih[col * 64 + k] : w_hh[(col - 256) * 64 + k];
        sm[OFF_WL + swz(col, k)] = v;
    }
    for (int idx = tid; idx < 64 * 64; idx += NTHREADS) {
        int k = idx >> 6, h = idx & 63;
        sm[OFF_WG + swz(h, k)]      = g1w[k * 64 + h];
        sm[OFF_WG + swz(64 + h, k)] = g2w[k * 64 + h];
    }
    for (int idx = tid; idx < 32 * 64; idx += NTHREADS) {
        int k = idx >> 5, j = idx & 31;
        sm[OFF_WD1 + swz(j, k)] = dw1[k * 32 + j];
    }
    for (int idx = tid; idx < 704; idx += NTHREADS) sm[OFF_ENCW + idx] = enc_w[idx];
    if (tid < 192) sm[OFF_DW2 + tid] = dw2[tid];
    if (tid < 64) {
        sm[OFF_ENCB + tid] = enc_b[tid];
        sm[OFF_G1B + tid]  = g1b[tid];
        sm[OFF_G2B + tid]  = g2b[tid];
    }
    if (tid < 256) sm[OFF_BSUM + tid] = b_ih[tid] + b_hh[tid];
    if (tid < 32)  sm[OFF_DB1 + tid] = db1[tid];
    if (tid < 6)   sm[OFF_DB2 + tid] = db2[tid];
    __syncthreads();   // ONLY block-wide barrier

    // ================= per-pair setup =================
    const size_t b = (size_t)blockIdx.x * NP + pr;
    float* PW   = sm + OFF_PW + pr * PW_FLOATS;
    float* SB   = PW + PSB;
    float* HB   = PW + PHB;
    float* X0   = PW + PX0;
    float* ADJ  = PW + PADJ;
    float* PRED = PW + PPRED;
    float* STAT = PW + PSTAT;

    if (wip == 0) {
        // adjacency normalize (single warp)
        #pragma unroll
        for (int rep = 0; rep < 2; rep++) {
            int e = lane + 32 * rep;
            if (e < 49) {
                int i = e / 7, j = e - 7 * i;
                float v = adj[b * 49 + e];
                if (i == j) v = 1.0f;
                ADJ[i * 8 + j] = v;
            }
        }
        __syncwarp();
        if (lane < 7) {
            float s = 0.f;
            #pragma unroll
            for (int j = 0; j < 7; j++) s += ADJ[lane * 8 + j];
            ADJ[lane * 8 + 7] = rsqrtf(fmaxf(s, 1.0f));
        }
        __syncwarp();
        #pragma unroll
        for (int rep = 0; rep < 2; rep++) {
            int e = lane + 32 * rep;
            if (e < 49) {
                int i = e / 7, j = e - 7 * i;
                ADJ[i * 8 + j] *= ADJ[i * 8 + 7] * ADJ[j * 8 + 7];
            }
        }
    } else {
        // pred/stat from last history row
        const float* xl = x_history + (b * NT + (NT - 1)) * 77;
        #pragma unroll
        for (int rep = 0; rep < 3; rep++) {
            int e = lane + 32 * rep;
            if (e < 77) {
                int n = e / 11, k = e - 11 * n;
                float v = xl[e];
                if (k < 6) PRED[n * 6 + k] = v;
                else       STAT[n * 5 + (k - 6)] = v;
            }
        }
    }
    // state init (each warp its h-half)
    float cxr[7];
    #pragma unroll
    for (int n = 0; n < 7; n++) { cxr[n] = 0.f; HB[n * 64 + hme] = 0.f; }

    // prefetch history row 0 (pair-cooperative: e = wip*32+lane, e+64)
    const int exs = wip * 32 + lane;
    float xpA, xpB = 0.f;
    {
        const float* xr = x_history + b * NT * 77;
        xpA = xr[exs];
        if (exs + 64 < 77) xpB = xr[exs + 64];
    }
    asm volatile("bar.sync %0, %1;" :: "r"(pbid), "n"(64) : "memory");

    const float* wl  = sm + OFF_WL;
    const float* wg  = sm + OFF_WG;
    const float* wd1 = sm + OFF_WD1;

    #define PBAR() asm volatile("bar.sync %0, %1;" :: "r"(pbid), "n"(64) : "memory")

    for (int step = 0; step < NSTEP; ++step) {
        // ---- stage x_t into X0 (history steps); prefetch next ----
        if (step < NT) {
            if (exs < 77) X0[exs] = xpA;
            if (exs + 64 < 77) X0[exs + 64] = xpB;
            PBAR();
            if (step + 1 < NT) {
                const float* xr = x_history + (b * NT + step + 1) * 77;
                xpA = xr[exs];
                if (exs + 64 < 77) xpB = xr[exs + 64];
            }
        }

        // ---- encoder: relu(x @ enc_w + b) -> SB[n*64+hme] ----
        {
            float ea[7];
            #pragma unroll
            for (int n = 0; n < 7; n++) ea[n] = sm[OFF_ENCB + hme];
            #pragma unroll
            for (int k = 0; k < 11; k++) {
                float wk = sm[OFF_ENCW + k * 64 + hme];
                #pragma unroll
                for (int n = 0; n < 7; n++) {
                    float xv = (step < NT) ? X0[n * 11 + k]
                             : (k < 6 ? PRED[n * 6 + k] : STAT[n * 5 + (k - 6)]);
                    ea[n] = fmaf(xv, wk, ea[n]);
                }
            }
            #pragma unroll
            for (int n = 0; n < 7; n++)
                SB[n * 64 + hme] = fmaxf(ea[n], 0.f);
            PBAR();
        }

        // ---- two GCN layers ----
        #pragma unroll
        for (int layer = 0; layer < 2; layer++) {
            const float* wrow = wg + (layer * 64 + hme) * 64;
            u64 ga[7];
            #pragma unroll
            for (int n = 0; n < 7; n++) ga[n] = 0;
            #pragma unroll 4
            for (int q = 0; q < 16; q++) {
                int off = ((q + lane) & 15) * 4;
                ulonglong2 w = *(const ulonglong2*)(wrow + off);
                #pragma unroll
                for (int n = 0; n < 7; n++) {
                    ulonglong2 a = *(const ulonglong2*)(SB + n * 64 + 4 * q);
                    ga[n] = fma2(a.y, w.y, fma2(a.x, w.x, ga[n]));
                }
            }
            float tp[7];
            #pragma unroll
            for (int j = 0; j < 7; j++) tp[j] = hadd(ga[j]);
            PBAR();   // both warps done reading SB
            const float* gb = sm + (layer ? OFF_G2B : OFF_G1B);
            #pragma unroll
            for (int n = 0; n < 7; n++) {
                float acc = gb[hme];
                #pragma unroll
                for (int j = 0; j < 7; j++)
                    acc = fmaf(ADJ[n * 8 + j], tp[j], acc);
                SB[n * 64 + hme] = fmaxf(acc, 0.f);
            }
            PBAR();
        }

        // ---- LSTM gates (pair-split: W0 i,f | W1 g,o) ----
        {
            u64 gc[28];
            #pragma unroll
            for (int i = 0; i < 28; i++) gc[i] = 0;
            const int cbase = lane + 128 * wip;
            #pragma unroll 2
            for (int q = 0; q < 16; q++) {
                int off = ((q + lane) & 15) * 4;
                ulonglong2 wi[4], wh[4];
                #pragma unroll
                for (int jj = 0; jj < 4; jj++) {
                    int col = cbase + 32 * jj;
                    wi[jj] = *(const ulonglong2*)(wl + col * 64 + off);
                    wh[jj] = *(const ulonglong2*)(wl + (256 + col) * 64 + off);
                }
                #pragma unroll
                for (int n = 0; n < 7; n++) {
                    ulonglong2 sa = *(const ulonglong2*)(SB + n * 64 + 4 * q);
                    ulonglong2 ha = *(const ulonglong2*)(HB + n * 64 + 4 * q);
                    #pragma unroll
                    for (int jj = 0; jj < 4; jj++) {
                        u64 a = gc[n * 4 + jj];
                        a = fma2(sa.x, wi[jj].x, a);
                        a = fma2(sa.y, wi[jj].y, a);
                        a = fma2(ha.x, wh[jj].x, a);
                        a = fma2(ha.y, wh[jj].y, a);
                        gc[n * 4 + jj] = a;
                    }
                }
            }
            float bb0 = sm[OFF_BSUM + cbase];
            float bb1 = sm[OFF_BSUM + cbase + 32];
            float bb2 = sm[OFF_BSUM + cbase + 64];
            float bb3 = sm[OFF_BSUM + cbase + 96];
            float k0[7], k1[7];   // kept gates: W0 -> i(lane), f(lane); W1 -> g(lane+32), o(lane+32)
            PBAR();   // both warps done reading SB/HB; SB and X0 free for exchange
            if (wip == 0) {
                #pragma unroll
                for (int n = 0; n < 7; n++) {
                    k0[n] = hadd(gc[n * 4 + 0]) + bb0;              // i(lane)
                    k1[n] = hadd(gc[n * 4 + 2]) + bb2;              // f(lane)
                    X0[n * 32 + lane]       = hadd(gc[n * 4 + 1]) + bb1;  // i(lane+32)
                    X0[224 + n * 32 + lane] = hadd(gc[n * 4 + 3]) + bb3;  // f(lane+32)
                }
            } else {
                #pragma unroll
                for (int n = 0; n < 7; n++) {
                    k0[n] = hadd(gc[n * 4 + 1]) + bb1;              // g(lane+32)
                    k1[n] = hadd(gc[n * 4 + 3]) + bb3;              // o(lane+32)
                    SB[n * 32 + lane]       = hadd(gc[n * 4 + 0]) + bb0;  // g(lane)
                    SB[224 + n * 32 + lane] = hadd(gc[n * 4 + 2]) + bb2;  // o(lane)
                }
            }
            PBAR();   // exchange visible
            if (wip == 0) {
                #pragma unroll
                for (int n = 0; n < 7; n++) {
                    float gg = SB[n * 32 + lane];
                    float go = SB[224 + n * 32 + lane];
                    float c = sigf(k1[n]) * cxr[n] + sigf(k0[n]) * tanhfast(gg);
                    cxr[n] = c;
                    HB[n * 64 + lane] = sigf(go) * tanhfast(c);
                }
            } else {
                #pragma unroll
                for (int n = 0; n < 7; n++) {
                    float gi = X0[n * 32 + lane];
                    float gf = X0[224 + n * 32 + lane];
                    float c = sigf(gf) * cxr[n] + sigf(gi) * tanhfast(k0[n]);
                    cxr[n] = c;
                    HB[n * 64 + lane + 32] = sigf(k1[n]) * tanhfast(c);
                }
            }
            PBAR();   // HB complete
        }

        // ---- decoder (future steps) ----
        if (step >= NT) {
            // dbuf(7x32): W0 nodes 0..3, W1 nodes 4..6; column j = lane
            const int nlo = wip ? 4 : 0;
            const int nhi = wip ? 7 : 4;
            u64 da[4];
            #pragma unroll
            for (int i = 0; i < 4; i++) da[i] = 0;
            #pragma unroll 4
            for (int q = 0; q < 16; q++) {
                int off = ((q + lane) & 15) * 4;
                ulonglong2 w = *(const ulonglong2*)(wd1 + lane * 64 + off);
                for (int n = nlo; n < nhi; n++) {
                    ulonglong2 a = *(const ulonglong2*)(HB + n * 64 + 4 * q);
                    da[n - nlo] = fma2(a.y, w.y, fma2(a.x, w.x, da[n - nlo]));
                }
            }
            float d1b = sm[OFF_DB1 + lane];
            for (int n = nlo; n < nhi; n++)
                X0[n * 32 + lane] = fmaxf(hadd(da[n - nlo]) + d1b, 0.f);
            PBAR();
            int idx = wip * 32 + lane;
            if (idx < 42) {
                int n = idx / 6, d = idx - 6 * n;
                float acc = sm[OFF_DB2 + d];
                const float* dr = X0 + n * 32;
                #pragma unroll
                for (int j = 0; j < 32; j++)
                    acc = fmaf(dr[j], sm[OFF_DW2 + j * 6 + d], acc);
                float p = PRED[idx] + tanhfast(acc) * 0.05f;
                p = fminf(fmaxf(p, 0.f), 1.0f);
                PRED[idx] = p;
                out[(b * FUT + (step - NT)) * 42 + idx] = p;
            }
            PBAR();   // PRED visible before next encoder
        }
    }
    #undef PBAR
}

extern "C" void kernel_launch(void* const* d_in, const int* in_sizes, int n_in,
                              void* d_out, int out_size)
{
    (void)in_sizes; (void)n_in; (void)out_size;
    static_assert(SMEM_FLOATS * 4 <= 232448, "smem too big");
    cudaFuncSetAttribute(stgnn_kernel,
                         cudaFuncAttributeMaxDynamicSharedMemorySize,
                         SMEM_FLOATS * 4);
    stgnn_kernel<<<GRID, NTHREADS, SMEM_FLOATS * 4>>>(
        (const float*)d_in[0],  (const float*)d_in[1],
        (const float*)d_in[2],  (const float*)d_in[3],
        (const float*)d_in[4],  (const float*)d_in[5],
        (const float*)d_in[6],  (const float*)d_in[7],
        (const float*)d_in[8],  (const float*)d_in[9],
        (const float*)d_in[10], (const float*)d_in[11],
        (const float*)d_in[12], (const float*)d_in[13],
        (const float*)d_in[14], (const float*)d_in[15],
        (float*)d_out);
}